// round 1
// baseline (speedup 1.0000x reference)
#include <cuda_runtime.h>
#include <math.h>

// ---------------------------------------------------------------------------
// SiamFC head:
//   x' = gelu(x + dw3x3(x,wx) + bx)   (64,64,96,96)
//   z' = gelu(z + dw3x3(z,wz) + bz)   (64,64,16,16)
//   out[b,i,j] = 0.001 * sum_{c,p,q} z'[b,c,p,q] * x'[b,c,i+p-8, j+q-8]
//   out: (64,1,97,97) fp32
//
// Strategy (round 0 baseline): fp32 SIMT, compute-bound on FFMA pipe.
// x' stored zero-padded in a __device__ scratch XP[b][c][128][120] so the
// correlation inner loop has no boundary logic (pad rows/cols stay zero from
// module-load zero-init and are never written).
// ---------------------------------------------------------------------------

__device__ float XP[64 * 64 * 128 * 120];  // padded x': rows 8..103, cols 8..103 valid
__device__ float ZPd[64 * 64 * 256];       // z': [b][c][16][16]

__device__ __forceinline__ float gelu_exact(float v) {
    return 0.5f * v * (1.0f + erff(v * 0.70710678118654752f));
}

// ---- Kernel A: preprocess x -> XP (one CTA per (b,c) plane) -----------------
__global__ __launch_bounds__(256) void prep_x(const float* __restrict__ x,
                                              const float* __restrict__ wx,
                                              const float* __restrict__ bx) {
    int bc = blockIdx.x;        // b*64 + c
    int c  = bc & 63;
    __shared__ float sp[98 * 100];  // zero-padded 96x96 plane (halo 1)

    for (int i = threadIdx.x; i < 98 * 100; i += 256) sp[i] = 0.0f;
    __syncthreads();

    const float* xp = x + (size_t)bc * 9216;
    for (int i = threadIdx.x; i < 9216; i += 256) {
        int r = i / 96, cl = i - r * 96;
        sp[(r + 1) * 100 + (cl + 1)] = xp[i];
    }
    __syncthreads();

    float w[9];
#pragma unroll
    for (int k = 0; k < 9; ++k) w[k] = __ldg(wx + c * 9 + k);
    float bias = __ldg(bx + c);

    float* dst = XP + (size_t)bc * (128 * 120);
    for (int i = threadIdx.x; i < 9216; i += 256) {
        int r = i / 96, cl = i - r * 96;
        float conv = bias;
#pragma unroll
        for (int di = 0; di < 3; ++di)
#pragma unroll
            for (int dj = 0; dj < 3; ++dj)
                conv = fmaf(w[di * 3 + dj], sp[(r + di) * 100 + (cl + dj)], conv);
        float v = sp[(r + 1) * 100 + (cl + 1)];
        dst[(r + 8) * 120 + (cl + 8)] = gelu_exact(v + conv);
    }
}

// ---- Kernel B: preprocess z -> ZPd (one CTA per (b,c) plane, 1 px/thread) ---
__global__ __launch_bounds__(256) void prep_z(const float* __restrict__ z,
                                              const float* __restrict__ wz,
                                              const float* __restrict__ bz) {
    int bc = blockIdx.x;
    int c  = bc & 63;
    __shared__ float sp[18 * 18];

    for (int i = threadIdx.x; i < 18 * 18; i += 256) sp[i] = 0.0f;
    __syncthreads();

    int t = threadIdx.x;  // 0..255 -> (p,q)
    int p = t >> 4, q = t & 15;
    sp[(p + 1) * 18 + (q + 1)] = z[(size_t)bc * 256 + t];
    __syncthreads();

    float conv = __ldg(bz + c);
#pragma unroll
    for (int di = 0; di < 3; ++di)
#pragma unroll
        for (int dj = 0; dj < 3; ++dj)
            conv = fmaf(__ldg(wz + c * 9 + di * 3 + dj), sp[(p + di) * 18 + (q + dj)], conv);
    float v = sp[(p + 1) * 18 + (q + 1)];
    ZPd[(size_t)bc * 256 + t] = gelu_exact(v + conv);
}

// ---- Kernel C: correlation --------------------------------------------------
// Grid (13, 64): blockIdx.x = 8-row output block, blockIdx.y = batch.
// 128 threads = 4 warps; warp w owns output rows i0+2w, i0+2w+1.
// Lane L (<=24) owns output cols 4L..4L+3 (lane 24 tail is predicated).
// Per channel: stage 23x120 x'-window + 16x16 z into SMEM, then slide the
// 16x16 template; FFMA-bound inner loop (128 FMA per window row).
__global__ __launch_bounds__(128) void corr(float* __restrict__ out) {
    int ib = blockIdx.x, b = blockIdx.y;
    int i0 = ib * 8;
    int tid = threadIdx.x;
    int w   = tid >> 5;
    int lane = tid & 31;
    int jb = (lane <= 24) ? (lane * 4) : 0;  // idle lanes recompute col 0 block (not stored)

    __shared__ __align__(16) float zc[256];
    __shared__ __align__(16) float xw[23 * 120];

    float acc0[4] = {0.f, 0.f, 0.f, 0.f};
    float acc1[4] = {0.f, 0.f, 0.f, 0.f};

    const float4* zsrc = reinterpret_cast<const float4*>(ZPd + (size_t)b * 64 * 256);

    for (int c = 0; c < 64; ++c) {
        __syncthreads();
        if (tid < 64)
            reinterpret_cast<float4*>(zc)[tid] = zsrc[c * 64 + tid];
        const float4* src =
            reinterpret_cast<const float4*>(XP + (size_t)(((b * 64 + c) * 128) + i0) * 120);
        for (int k = tid; k < 690; k += 128)  // 23*120/4 float4
            reinterpret_cast<float4*>(xw)[k] = src[k];
        __syncthreads();

#pragma unroll 1
        for (int k = 0; k < 17; ++k) {  // window row = i0 + 2w + k
            const float* wp = xw + (2 * w + k) * 120 + jb;
            float win[20];
#pragma unroll
            for (int v = 0; v < 5; ++v) {
                float4 t = reinterpret_cast<const float4*>(wp)[v];
                win[4 * v + 0] = t.x; win[4 * v + 1] = t.y;
                win[4 * v + 2] = t.z; win[4 * v + 3] = t.w;
            }
            if (k < 16) {  // rw=0, p=k
                const float* zp = zc + k * 16;
                float zr[16];
#pragma unroll
                for (int v = 0; v < 4; ++v) {
                    float4 t = reinterpret_cast<const float4*>(zp)[v];
                    zr[4 * v + 0] = t.x; zr[4 * v + 1] = t.y;
                    zr[4 * v + 2] = t.z; zr[4 * v + 3] = t.w;
                }
#pragma unroll
                for (int q = 0; q < 16; ++q)
#pragma unroll
                    for (int cc = 0; cc < 4; ++cc)
                        acc0[cc] = fmaf(zr[q], win[q + cc], acc0[cc]);
            }
            if (k >= 1) {  // rw=1, p=k-1
                const float* zp = zc + (k - 1) * 16;
                float zr[16];
#pragma unroll
                for (int v = 0; v < 4; ++v) {
                    float4 t = reinterpret_cast<const float4*>(zp)[v];
                    zr[4 * v + 0] = t.x; zr[4 * v + 1] = t.y;
                    zr[4 * v + 2] = t.z; zr[4 * v + 3] = t.w;
                }
#pragma unroll
                for (int q = 0; q < 16; ++q)
#pragma unroll
                    for (int cc = 0; cc < 4; ++cc)
                        acc1[cc] = fmaf(zr[q], win[q + cc], acc1[cc]);
            }
        }
    }

    if (lane <= 24) {
        int irow = i0 + 2 * w;
#pragma unroll
        for (int cc = 0; cc < 4; ++cc) {
            int j = jb + cc;
            if (j < 97) {
                if (irow < 97)
                    out[(size_t)b * 9409 + irow * 97 + j] = acc0[cc] * 0.001f;
                if (irow + 1 < 97)
                    out[(size_t)b * 9409 + (irow + 1) * 97 + j] = acc1[cc] * 0.001f;
            }
        }
    }
}

// ---- launch ----------------------------------------------------------------
extern "C" void kernel_launch(void* const* d_in, const int* in_sizes, int n_in,
                              void* d_out, int out_size) {
    const float* z  = (const float*)d_in[0];
    const float* x  = (const float*)d_in[1];
    const float* wz = (const float*)d_in[2];
    const float* bz = (const float*)d_in[3];
    const float* wx = (const float*)d_in[4];
    const float* bx = (const float*)d_in[5];
    float* out = (float*)d_out;

    prep_x<<<4096, 256>>>(x, wx, bx);
    prep_z<<<4096, 256>>>(z, wz, bz);
    corr<<<dim3(13, 64), 128>>>(out);
}